// round 15
// baseline (speedup 1.0000x reference)
#include <cuda_runtime.h>

// ---------------- problem constants ----------------
namespace {
constexpr int BATCH   = 2048;
constexpr int NTIME   = 2048;
constexpr int SEASLEN = 2055;          // 7 + 1 + 2047
constexpr int W       = 288;           // len(arange(0, 2014, 7))
constexpr int CH      = 67;            // 28 (y_in) + 35 (X) + 4 (S)
constexpr int OCH     = 7;             // outsample channels
constexpr int NC      = 64;            // chunks
constexpr int WU      = 280;           // warmup steps = 40 cycles (mult of 7)
constexpr int B1      = 280;           // chunk 0 body length (40*7)
constexpr int CL      = 28;            // chunk i>=1 body (4*7), last = 31
constexpr int SP      = 68;            // 64x64 tile smem row stride
constexpr int NWIN    = W * BATCH / 64;        // 9216 window blocks (64 pairs)
constexpr int NFIX    = 65 * 32;               // 2080 fix blocks
constexpr long long INS_ELEMS  = (long long)W * BATCH * CH;  // 39,518,208
constexpr long long OUTS_ELEMS = (long long)W * BATCH * 7;   //  4,128,768
constexpr long long LEV_ELEMS  = (long long)BATCH * NTIME;   //  4,194,304
}

__device__ __forceinline__ int chunk_of(int t) {      // writer of levels[t]
    return (t <= B1) ? 0 : min(NC - 1, 1 + (t - (B1 + 1)) / CL);
}
__device__ __forceinline__ int body_start(int ci) {   // ci >= 1
    return B1 + (ci - 1) * CL;
}

// ---------------- scratch (time-major: [t][b]) ------------------------------
__device__ float g_Yt  [NTIME * BATCH];
__device__ float g_levT[NTIME * BATCH];   // raw levels, [t][b]
__device__ float g_seaT[SEASLEN * BATCH]; // raw seasonal, [j][b]
__device__ float g_LT  [NTIME * BATCH];   // raw log(Y/seas), [t][b]
__device__ float g_LL  [W * BATCH];       // raw log(lev) at t=7w+27, [w][b]
__device__ float g_St  [4 * BATCH];       // S transposed
__device__ float g_anchor[NC * BATCH];
__device__ float g_gamma [NC * BATCH];    // true = raw * gamma
__device__ float g_lgam  [NC * BATCH];
__device__ float g_rgam  [NC * BATCH];    // 1/gamma

// ---------------- Y transpose: 64x64 tiles, float4 both sides ---------------
__global__ void transpose_Y(const float* __restrict__ Y)
{
    __shared__ float sm[64 * SP];        // sm[t_local][b_local]
    int t0 = blockIdx.x * 64;
    int b0 = blockIdx.y * 64;
    int tid = threadIdx.x;               // 256
#pragma unroll
    for (int p = 0; p < 4; p++) {        // load: rows = b, cols = t
        int f  = tid + 256 * p;
        int r  = f >> 4;                 // b_local
        int c4 = f & 15;                 // t_local/4
        float4 v = *(const float4*)&Y[(long long)(b0 + r) * NTIME + t0 + 4 * c4];
        sm[(4 * c4 + 0) * SP + r] = v.x;
        sm[(4 * c4 + 1) * SP + r] = v.y;
        sm[(4 * c4 + 2) * SP + r] = v.z;
        sm[(4 * c4 + 3) * SP + r] = v.w;
    }
    __syncthreads();
#pragma unroll
    for (int p = 0; p < 4; p++) {        // store: rows = t, cols = b
        int f  = tid + 256 * p;
        int tt = f >> 4;
        int c4 = f & 15;
        float4 v = *(const float4*)&sm[tt * SP + 4 * c4];
        *(float4*)&g_Yt[(long long)(t0 + tt) * BATCH + b0 + 4 * c4] = v;
    }
}

// ---------------- kernel 1: chunked speculative ES scan (2 rows/thread) -----
// Each thread advances TWO independent recurrences (rows b and b+1024) so the
// per-warp MUFU/FMA dependency chains interleave; row-2 addresses are constant
// +1024-float immediate offsets from row-1 pointers.
__global__ void es_scan(const int*   __restrict__ idxs,
                        const float* __restrict__ emb)
{
    int b  = blockIdx.x * blockDim.x + threadIdx.x;   // 0..1023
    int ci = blockIdx.y;

    const float* e1 = emb + (long long)idxs[b] * 9;
    const float* e2 = emb + (long long)idxs[b + 1024] * 9;
    float a1  = 1.f / (1.f + __expf(-e1[0]));
    float bs1 = 1.f / (1.f + __expf(-e1[1]));
    float a2  = 1.f / (1.f + __expf(-e2[0]));
    float bs2 = 1.f / (1.f + __expf(-e2[1]));
    float am1 = 1.f - a1, bsm1 = 1.f - bs1;
    float am2 = 1.f - a2, bsm2 = 1.f - bs2;

    const float* yp = g_Yt  + b;
    float*       lvp= g_levT+ b;
    float*       sep= g_seaT+ b;
    float*       lp = g_LT  + b;

    float buf1[7], buf2[7];
    float lev1, lev2;
    int   k, body;

    if (ci == 0) {
        float is01 = __expf(e1[2]);
        float is02 = __expf(e2[2]);
#pragma unroll
        for (int j = 0; j < 6; j++) { buf1[j] = __expf(e1[3 + j]); buf2[j] = __expf(e2[3 + j]); }
        buf1[6] = is01; buf2[6] = is02;
        sep[0] = is01; sep[1024] = is02;
#pragma unroll
        for (int j = 0; j < 6; j++) {
            sep[((1 + j) << 11)]        = buf1[j];
            sep[((1 + j) << 11) + 1024] = buf2[j];
        }
        sep[(7 << 11)]        = is01;
        sep[(7 << 11) + 1024] = is02;
        lev1 = __fdividef(yp[0],    is01);
        lev2 = __fdividef(yp[1024], is02);
        lvp[0] = lev1; lvp[1024] = lev2;
        lp[0]  = __logf(lev1); lp[1024] = __logf(lev2);
        k = 0;
        body = B1;
    } else {
        int bstart = body_start(ci);          // mult of 7
        k = bstart - WU;
        lev1 = yp[(k << 11)];
        lev2 = yp[(k << 11) + 1024];
#pragma unroll
        for (int j = 0; j < 7; j++) { buf1[j] = 1.0f; buf2[j] = 1.0f; }

        // warmup: double-buffered prefetch, immediate-offset addressing
        const float* ypg = yp + ((k + 1) << 11);
        float yv1[7], yv2[7];
#pragma unroll
        for (int j = 0; j < 7; j++) {
            yv1[j] = ypg[(j << 11)];
            yv2[j] = ypg[(j << 11) + 1024];
        }
        for (int g = 0; g < WU / 7; g++) {
            float yn1[7], yn2[7];
#pragma unroll
            for (int j = 0; j < 7; j++) {
                yn1[j] = ypg[((j + 7) << 11)];
                yn2[j] = ypg[((j + 7) << 11) + 1024];
            }
#pragma unroll
            for (int sl = 0; sl < 7; sl++) {
                float y1 = yv1[sl], s1 = buf1[sl];
                float y2 = yv2[sl], s2 = buf2[sl];
                float q1 = __fdividef(y1, s1);
                float q2 = __fdividef(y2, s2);
                float n1 = fmaf(a1, q1, am1 * lev1);
                float n2 = fmaf(a2, q2, am2 * lev2);
                buf1[sl] = fmaf(bs1, __fdividef(y1, n1), bsm1 * s1);
                buf2[sl] = fmaf(bs2, __fdividef(y2, n2), bsm2 * s2);
                lev1 = n1; lev2 = n2;
            }
            ypg += 7 << 11;
#pragma unroll
            for (int j = 0; j < 7; j++) { yv1[j] = yn1[j]; yv2[j] = yn2[j]; }
        }
        k = bstart;
        g_anchor[ci * BATCH + b]        = lev1;
        g_anchor[ci * BATCH + b + 1024] = lev2;
        body = (ci == NC - 1) ? (NTIME - 1 - bstart) : CL;
    }

    int nfull = body / 7;
    int tail  = body % 7;

    const float* ypg = yp + ((k + 1) << 11);
    float* lvg = lvp + ((k + 1) << 11);
    float* seg = sep + ((8 + k) << 11);
    float* lg  = lp  + ((k + 1) << 11);
    int    wgi = k / 7 - 3;               // g_LL row for this group (sl==5)

    for (int g = 0; g < nfull; g++) {
        float yv1[7], yv2[7];
#pragma unroll
        for (int j = 0; j < 7; j++) {
            yv1[j] = ypg[(j << 11)];
            yv2[j] = ypg[(j << 11) + 1024];
        }
#pragma unroll
        for (int sl = 0; sl < 7; sl++) {
            float y1 = yv1[sl], s1 = buf1[sl];
            float y2 = yv2[sl], s2 = buf2[sl];
            float q1 = __fdividef(y1, s1);
            float q2 = __fdividef(y2, s2);
            float n1 = fmaf(a1, q1, am1 * lev1);
            float n2 = fmaf(a2, q2, am2 * lev2);
            float ns1 = fmaf(bs1, __fdividef(y1, n1), bsm1 * s1);
            float ns2 = fmaf(bs2, __fdividef(y2, n2), bsm2 * s2);
            buf1[sl] = ns1; buf2[sl] = ns2;
            lev1 = n1; lev2 = n2;
            lvg[(sl << 11)]        = n1;
            lvg[(sl << 11) + 1024] = n2;
            seg[(sl << 11)]        = ns1;
            seg[(sl << 11) + 1024] = ns2;
            lg [(sl << 11)]        = __logf(q1);    // s == seasonal_raw[k+1]
            lg [(sl << 11) + 1024] = __logf(q2);
            if (sl == 5 && (unsigned)wgi < (unsigned)W) {
                g_LL[wgi * BATCH + b]        = __logf(n1);
                g_LL[wgi * BATCH + b + 1024] = __logf(n2);
            }
        }
        ypg += 7 << 11; lvg += 7 << 11; seg += 7 << 11; lg += 7 << 11;
        wgi += 1;
        k   += 7;
    }
#pragma unroll
    for (int sl = 0; sl < 6; sl++) {
        if (sl < tail) {
            float y1 = yp[((k + 1) << 11)];
            float y2 = yp[((k + 1) << 11) + 1024];
            float s1 = buf1[sl], s2 = buf2[sl];
            float q1 = __fdividef(y1, s1);
            float q2 = __fdividef(y2, s2);
            float n1 = fmaf(a1, q1, am1 * lev1);
            float n2 = fmaf(a2, q2, am2 * lev2);
            float ns1 = fmaf(bs1, __fdividef(y1, n1), bsm1 * s1);
            float ns2 = fmaf(bs2, __fdividef(y2, n2), bsm2 * s2);
            buf1[sl] = ns1; buf2[sl] = ns2;
            lev1 = n1; lev2 = n2;
            lvp[((k + 1) << 11)]        = n1;
            lvp[((k + 1) << 11) + 1024] = n2;
            sep[((8 + k) << 11)]        = ns1;
            sep[((8 + k) << 11) + 1024] = ns2;
            lp [((k + 1) << 11)]        = __logf(q1);
            lp [((k + 1) << 11) + 1024] = __logf(q2);
            if (sl == 5 && (unsigned)(k - 26) <= 2009u) {
                g_LL[((k - 26) / 7) * BATCH + b]        = __logf(n1);
                g_LL[((k - 26) / 7) * BATCH + b + 1024] = __logf(n2);
            }
            k++;
        }
    }
}

// ---------------- kernel 2: per-row scale combine (grouped MLP) -------------
__global__ void combine_gamma(const float* __restrict__ S)
{
    int b = blockIdx.x * blockDim.x + threadIdx.x;
    if (b >= BATCH) return;

    float g = 1.0f;
    g_gamma[b] = 1.0f; g_lgam[b] = 0.0f; g_rgam[b] = 1.0f;
    for (int i0 = 1; i0 < NC; i0 += 7) {        // 63 = 9*7 exact
        float r[7];
#pragma unroll
        for (int j = 0; j < 7; j++) {           // 14 independent loads
            int i = i0 + j;
            float prev = g_levT[body_start(i) * BATCH + b];
            float anc  = g_anchor[i * BATCH + b];
            r[j] = __fdividef(prev, anc);
        }
#pragma unroll
        for (int j = 0; j < 7; j++) {
            int i = i0 + j;
            g *= r[j];
            g_gamma[i * BATCH + b] = g;
            g_lgam [i * BATCH + b] = __logf(g);
            g_rgam [i * BATCH + b] = __fdividef(1.0f, g);
        }
    }
#pragma unroll
    for (int j = 0; j < 4; j++) g_St[j * BATCH + b] = S[b * 4 + j];
}

// ---------------- kernel 3: windows (64 pairs/block) + fix, ONE launch -------
__global__ void win_and_fix(const float* __restrict__ X,
                            const float* __restrict__ Y,
                            float* __restrict__ ins, float* __restrict__ outs,
                            float* __restrict__ levels,
                            float* __restrict__ seasonal)
{
    __shared__ __align__(16) float pool[64 * CH + 64 * OCH];   // 18.9 KB
    int tid = threadIdx.x;

    if (blockIdx.x < NWIN) {
        // ================= window role: 64 (w,b) pairs =================
        float* ti = pool;                 // 64*CH = 4288 floats, linear
        float* to = pool + 64 * CH;       // 64*OCH = 448 floats, linear
        int bw0  = blockIdx.x * 64;       // 2048 % 64 == 0 -> single w
        int w    = bw0 >> 11;
        int ws   = w * 7;
        int b0   = bw0 & (BATCH - 1);
        int lane = tid & 31;
        int warp = tid >> 5;

        // part A: 28 log + 4 S channels. Warps 0-3 own half 0 (pl=lane),
        // warps 4-7 own half 1 (pl=32+lane); each warp covers channels
        // c = (warp&3) + 4i, so pair-constants load ONCE per warp.
        {
            int h  = warp >> 2;
            int wq = warp & 3;
            int pl = 32 * h + lane;
            int b  = b0 + pl;
            int chA = chunk_of(ws);       // chunks for t in [ws,ws+27] are all
            int chB = chunk_of(ws + 27);  // chA or chB (span 28 <= CL)
            float lgA = g_lgam[chA * BATCH + b];
            float lgB = (chB == chA) ? lgA : g_lgam[chB * BATCH + b];
            float LLc = g_LL[w * BATCH + b] + lgB;
#pragma unroll
            for (int i = 0; i < 8; i++) {
                int c = wq + 4 * i;                   // 0..31
                if (c < 28) {
                    int t = ws + c;
                    float lg = (chunk_of(t) == chA) ? lgA : lgB;
                    ti[pl * CH + c] = g_LT[t * BATCH + b] + lg - LLc;
                } else {
                    ti[pl * CH + 63 + (c - 28)] = g_St[(c - 28) * BATCH + b];
                }
            }
        }
        // part B1: 35 X channels, lanes span c (coalesced row-major reads)
        for (int i = tid; i < 64 * 35; i += 256) {
            int bl = i / 35;
            int c  = i - bl * 35;
            ti[bl * CH + 28 + c] = X[(b0 + bl) * NTIME + ws + c];
        }
        // part B2: 7 outsample-Y channels (linear tile == output order)
#pragma unroll
        for (int p = 0; p < 2; p++) {
            int i = tid + 256 * p;
            if (i < 64 * OCH) {
                int bl = i / OCH;
                int c  = i - bl * OCH;
                to[i] = Y[(b0 + bl) * NTIME + ws + 28 + c];
            }
        }
        __syncthreads();

        // phase 2: straight float4 copies, streaming stores
        const float4* ti4 = (const float4*)ti;
        float4* ins4 = (float4*)(ins + (long long)bw0 * CH);   // 1072 float4
#pragma unroll
        for (int p = 0; p < 4; p++) {
            int j = tid + 256 * p;
            __stcs(&ins4[j], ti4[j]);
        }
        {
            int j = tid + 1024;
            if (j < 1072) __stcs(&ins4[j], ti4[j]);
        }
        if (tid < 112) {
            float4* outs4 = (float4*)(outs + (long long)bw0 * OCH);
            __stcs(&outs4[tid], ((const float4*)to)[tid]);
        }
    } else {
        // ================= fix role =================
        float* sm = pool;                 // 64*SP floats fits in pool
        int fid = blockIdx.x - NWIN;      // 0 .. NFIX-1
        int bx  = fid % 65;
        int b0  = (fid / 65) * 64;
        if (bx < 32) {
            int t0 = bx * 64;
#pragma unroll
            for (int p = 0; p < 4; p++) {        // load: rows = t, cols = b (f4)
                int f  = tid + 256 * p;
                int r  = f >> 4;
                int c4 = f & 15;
                float4 v = __ldcs((const float4*)&g_levT[(long long)(t0 + r) * BATCH + b0 + 4 * c4]);
                sm[(4 * c4 + 0) * SP + r] = v.x;
                sm[(4 * c4 + 1) * SP + r] = v.y;
                sm[(4 * c4 + 2) * SP + r] = v.z;
                sm[(4 * c4 + 3) * SP + r] = v.w;
            }
            __syncthreads();
#pragma unroll
            for (int p = 0; p < 4; p++) {        // store: rows = b, cols = t (f4)
                int f  = tid + 256 * p;
                int bb = f >> 4;
                int c4 = f & 15;
                int b  = b0 + bb;
                int t  = t0 + 4 * c4;
                float4 v = *(const float4*)&sm[bb * SP + 4 * c4];
                v.x *= g_gamma[chunk_of(t + 0) * BATCH + b];
                v.y *= g_gamma[chunk_of(t + 1) * BATCH + b];
                v.z *= g_gamma[chunk_of(t + 2) * BATCH + b];
                v.w *= g_gamma[chunk_of(t + 3) * BATCH + b];
                __stcs((float4*)&levels[(long long)b * NTIME + t], v);
            }
        } else {
            int j0 = (bx - 32) * 64;             // 33 x-tiles cover 2055
#pragma unroll
            for (int p = 0; p < 4; p++) {
                int f  = tid + 256 * p;
                int r  = f >> 4;
                int c4 = f & 15;
                int j  = j0 + r;
                if (j < SEASLEN) {
                    float4 v = __ldcs((const float4*)&g_seaT[(long long)j * BATCH + b0 + 4 * c4]);
                    sm[(4 * c4 + 0) * SP + r] = v.x;
                    sm[(4 * c4 + 1) * SP + r] = v.y;
                    sm[(4 * c4 + 2) * SP + r] = v.z;
                    sm[(4 * c4 + 3) * SP + r] = v.w;
                }
            }
            __syncthreads();
#pragma unroll
            for (int q = 0; q < 16; q++) {       // scalar coalesced stores
                int f  = tid + 256 * q;          // 4096 elements
                int bb = f >> 6;
                int jj = f & 63;
                int j  = j0 + jj;
                if (j >= SEASLEN) continue;
                int b = b0 + bb;
                float v = sm[bb * SP + jj];
                if (j >= 8)                      // seasonal[8+k] written at t=k+1
                    v *= g_rgam[chunk_of(j - 7) * BATCH + b];
                __stcs(&seasonal[(long long)b * SEASLEN + j], v);
            }
        }
    }
}

// ---------------- launch -----------------------------------------------------
extern "C" void kernel_launch(void* const* d_in, const int* in_sizes, int n_in,
                              void* d_out, int out_size)
{
    const float* S    = (const float*)d_in[0];   // (2048, 4)
    const float* Y    = (const float*)d_in[1];   // (2048, 2048)
    const float* X    = (const float*)d_in[2];   // (2048, 1, 2048)
    const int*   idxs = (const int*)  d_in[3];   // (2048,)
    const float* emb  = (const float*)d_in[4];   // (100000, 9)

    float* out      = (float*)d_out;
    float* ins      = out;                                      // 39,518,208
    float* outs     = out + INS_ELEMS;                          //  4,128,768
    float* levels   = out + INS_ELEMS + OUTS_ELEMS;             //  4,194,304
    float* seasonal = out + INS_ELEMS + OUTS_ELEMS + LEV_ELEMS; // 2048*2055

    transpose_Y  <<<dim3(32, 32), 256>>>(Y);                    // 1
    es_scan      <<<dim3(8, NC), 128>>>(idxs, emb);             // 2 (2 rows/thr)
    combine_gamma<<<BATCH / 256, 256>>>(S);                     // 3
    win_and_fix  <<<NWIN + NFIX, 256>>>(X, Y, ins, outs,        // 4 (ncu slot)
                                        levels, seasonal);
}

// round 16
// speedup vs baseline: 1.1251x; 1.1251x over previous
#include <cuda_runtime.h>

// ---------------- problem constants ----------------
namespace {
constexpr int BATCH   = 2048;
constexpr int NTIME   = 2048;
constexpr int SEASLEN = 2055;          // 7 + 1 + 2047
constexpr int W       = 288;           // len(arange(0, 2014, 7))
constexpr int CH      = 67;            // 28 (y_in) + 35 (X) + 4 (S)
constexpr int OCH     = 7;             // outsample channels
constexpr int NC      = 64;            // chunks
constexpr int WU      = 280;           // warmup steps = 40 cycles (mult of 7)
constexpr int B1      = 280;           // chunk 0 body length (40*7)
constexpr int CL      = 28;            // chunk i>=1 body (4*7), last = 31
constexpr int SP      = 68;            // 64x64 tile smem row stride
constexpr int NWIN    = W * BATCH / 64;        // 9216 window blocks (64 pairs)
constexpr int NFIX    = 65 * 32;               // 2080 fix blocks
constexpr long long INS_ELEMS  = (long long)W * BATCH * CH;  // 39,518,208
constexpr long long OUTS_ELEMS = (long long)W * BATCH * 7;   //  4,128,768
constexpr long long LEV_ELEMS  = (long long)BATCH * NTIME;   //  4,194,304
}

__device__ __forceinline__ int chunk_of(int t) {      // writer of levels[t]
    return (t <= B1) ? 0 : min(NC - 1, 1 + (t - (B1 + 1)) / CL);
}
__device__ __forceinline__ int body_start(int ci) {   // ci >= 1
    return B1 + (ci - 1) * CL;
}

// ---------------- scratch (time-major: [t][b]) ------------------------------
__device__ float g_Yt  [NTIME * BATCH];
__device__ float g_levT[NTIME * BATCH];   // raw levels, [t][b]
__device__ float g_seaT[SEASLEN * BATCH]; // raw seasonal, [j][b]
__device__ float g_LT  [NTIME * BATCH];   // raw log(Y/seas), [t][b]
__device__ float g_LL  [W * BATCH];       // raw log(lev) at t=7w+27, [w][b]
__device__ float g_St  [4 * BATCH];       // S transposed
__device__ float g_anchor[NC * BATCH];
__device__ float g_gamma [NC * BATCH];    // true = raw * gamma
__device__ float g_lgam  [NC * BATCH];
__device__ float g_rgam  [NC * BATCH];    // 1/gamma

// ---------------- Y transpose: 64x64 tiles, float4 both sides ---------------
__global__ void transpose_Y(const float* __restrict__ Y)
{
    __shared__ float sm[64 * SP];        // sm[t_local][b_local]
    int t0 = blockIdx.x * 64;
    int b0 = blockIdx.y * 64;
    int tid = threadIdx.x;               // 256
#pragma unroll
    for (int p = 0; p < 4; p++) {        // load: rows = b, cols = t
        int f  = tid + 256 * p;
        int r  = f >> 4;                 // b_local
        int c4 = f & 15;                 // t_local/4
        float4 v = *(const float4*)&Y[(long long)(b0 + r) * NTIME + t0 + 4 * c4];
        sm[(4 * c4 + 0) * SP + r] = v.x;
        sm[(4 * c4 + 1) * SP + r] = v.y;
        sm[(4 * c4 + 2) * SP + r] = v.z;
        sm[(4 * c4 + 3) * SP + r] = v.w;
    }
    __syncthreads();
#pragma unroll
    for (int p = 0; p < 4; p++) {        // store: rows = t, cols = b
        int f  = tid + 256 * p;
        int tt = f >> 4;
        int c4 = f & 15;
        float4 v = *(const float4*)&sm[tt * SP + 4 * c4];
        *(float4*)&g_Yt[(long long)(t0 + tt) * BATCH + b0 + 4 * c4] = v;
    }
}

// ---------------- kernel 1: chunked speculative ES scan (1 row/thread) ------
__global__ void es_scan(const int*   __restrict__ idxs,
                        const float* __restrict__ emb)
{
    int b  = blockIdx.x * blockDim.x + threadIdx.x;
    int ci = blockIdx.y;

    const float* e = emb + (long long)idxs[b] * 9;
    float a   = 1.f / (1.f + __expf(-e[0]));
    float bs  = 1.f / (1.f + __expf(-e[1]));
    float am  = 1.f - a;
    float bsm = 1.f - bs;

    const float* yp = g_Yt  + b;
    float*       lvp= g_levT+ b;
    float*       sep= g_seaT+ b;
    float*       lp = g_LT  + b;

    float buf[7];
    float lev;
    int   k, body;

    if (ci == 0) {
        float is0 = __expf(e[2]);
#pragma unroll
        for (int j = 0; j < 6; j++) buf[j] = __expf(e[3 + j]);
        buf[6] = is0;
        sep[0] = is0;
#pragma unroll
        for (int j = 0; j < 6; j++) sep[(1 + j) << 11] = buf[j];
        sep[7 << 11] = is0;
        lev = __fdividef(yp[0], is0);
        lvp[0] = lev;
        lp[0]  = __logf(lev);
        k = 0;
        body = B1;
    } else {
        int bstart = body_start(ci);          // mult of 7
        k = bstart - WU;
        lev = yp[k << 11];
#pragma unroll
        for (int j = 0; j < 7; j++) buf[j] = 1.0f;

        // warmup: double-buffered prefetch, immediate-offset addressing
        const float* ypg = yp + ((k + 1) << 11);
        float yv[7];
#pragma unroll
        for (int j = 0; j < 7; j++) yv[j] = ypg[j << 11];
        for (int g = 0; g < WU / 7; g++) {
            float yn[7];
#pragma unroll
            for (int j = 0; j < 7; j++) yn[j] = ypg[(j + 7) << 11];
#pragma unroll
            for (int sl = 0; sl < 7; sl++) {
                float y  = yv[sl];
                float s  = buf[sl];
                float q  = __fdividef(y, s);
                float nl = fmaf(a, q, am * lev);
                float ns = fmaf(bs, __fdividef(y, nl), bsm * s);
                buf[sl] = ns;
                lev     = nl;
            }
            ypg += 7 << 11;
#pragma unroll
            for (int j = 0; j < 7; j++) yv[j] = yn[j];
        }
        k = bstart;
        g_anchor[ci * BATCH + b] = lev;
        body = (ci == NC - 1) ? (NTIME - 1 - bstart) : CL;
    }

    int nfull = body / 7;
    int tail  = body % 7;

    const float* ypg = yp + ((k + 1) << 11);
    float* lvg = lvp + ((k + 1) << 11);
    float* seg = sep + ((8 + k) << 11);
    float* lg  = lp  + ((k + 1) << 11);
    int    wgi = k / 7 - 3;               // g_LL row for this group (sl==5)

    for (int g = 0; g < nfull; g++) {
        float yv[7];
#pragma unroll
        for (int j = 0; j < 7; j++) yv[j] = ypg[j << 11];
#pragma unroll
        for (int sl = 0; sl < 7; sl++) {
            float y  = yv[sl];
            float s  = buf[sl];
            float q  = __fdividef(y, s);
            float nl = fmaf(a, q, am * lev);
            float ns = fmaf(bs, __fdividef(y, nl), bsm * s);
            buf[sl] = ns;
            lev     = nl;
            lvg[sl << 11] = nl;
            seg[sl << 11] = ns;
            lg [sl << 11] = __logf(q);     // s == seasonal_raw[k+1]
            if (sl == 5 && (unsigned)wgi < (unsigned)W)
                g_LL[wgi * BATCH + b] = __logf(nl);
        }
        ypg += 7 << 11; lvg += 7 << 11; seg += 7 << 11; lg += 7 << 11;
        wgi += 1;
        k   += 7;
    }
#pragma unroll
    for (int sl = 0; sl < 6; sl++) {
        if (sl < tail) {
            float y  = yp[(k + 1) << 11];
            float s  = buf[sl];
            float q  = __fdividef(y, s);
            float nl = fmaf(a, q, am * lev);
            float ns = fmaf(bs, __fdividef(y, nl), bsm * s);
            buf[sl] = ns;
            lev     = nl;
            lvp[(k + 1) << 11] = nl;
            sep[(8 + k) << 11] = ns;
            lp [(k + 1) << 11] = __logf(q);
            if (sl == 5 && (unsigned)(k - 26) <= 2009u)
                g_LL[((k - 26) / 7) * BATCH + b] = __logf(nl);
            k++;
        }
    }
}

// ---------------- kernel 2: per-row scale combine (grouped MLP) -------------
__global__ void combine_gamma(const float* __restrict__ S)
{
    int b = blockIdx.x * blockDim.x + threadIdx.x;
    if (b >= BATCH) return;

    float g = 1.0f;
    g_gamma[b] = 1.0f; g_lgam[b] = 0.0f; g_rgam[b] = 1.0f;
    for (int i0 = 1; i0 < NC; i0 += 7) {        // 63 = 9*7 exact
        float r[7];
#pragma unroll
        for (int j = 0; j < 7; j++) {           // 14 independent loads
            int i = i0 + j;
            float prev = g_levT[body_start(i) * BATCH + b];
            float anc  = g_anchor[i * BATCH + b];
            r[j] = __fdividef(prev, anc);
        }
#pragma unroll
        for (int j = 0; j < 7; j++) {
            int i = i0 + j;
            g *= r[j];
            g_gamma[i * BATCH + b] = g;
            g_lgam [i * BATCH + b] = __logf(g);
            g_rgam [i * BATCH + b] = __fdividef(1.0f, g);
        }
    }
#pragma unroll
    for (int j = 0; j < 4; j++) g_St[j * BATCH + b] = S[b * 4 + j];
}

// ---------------- kernel 3: windows (64 pairs/block) + fix, ONE launch -------
__global__ void win_and_fix(const float* __restrict__ X,
                            const float* __restrict__ Y,
                            float* __restrict__ ins, float* __restrict__ outs,
                            float* __restrict__ levels,
                            float* __restrict__ seasonal)
{
    __shared__ __align__(16) float pool[64 * CH + 64 * OCH];   // 18.9 KB
    int tid = threadIdx.x;

    if (blockIdx.x < NWIN) {
        // ================= window role: 64 (w,b) pairs =================
        float* ti = pool;                 // 64*CH = 4288 floats, linear
        float* to = pool + 64 * CH;       // 64*OCH = 448 floats, linear
        int bw0  = blockIdx.x * 64;       // 2048 % 64 == 0 -> single w
        int w    = bw0 >> 11;
        int ws   = w * 7;
        int b0   = bw0 & (BATCH - 1);
        int lane = tid & 31;
        int warp = tid >> 5;

        // part A: 28 log + 4 S channels. Warps 0-3 own half 0 (pl=lane),
        // warps 4-7 own half 1 (pl=32+lane); each warp covers channels
        // c = (warp&3) + 4i, so pair-constants load ONCE per warp.
        {
            int h  = warp >> 2;
            int wq = warp & 3;
            int pl = 32 * h + lane;
            int b  = b0 + pl;
            int chA = chunk_of(ws);       // chunks for t in [ws,ws+27] are all
            int chB = chunk_of(ws + 27);  // chA or chB (span 28 <= CL)
            float lgA = g_lgam[chA * BATCH + b];
            float lgB = (chB == chA) ? lgA : g_lgam[chB * BATCH + b];
            float LLc = g_LL[w * BATCH + b] + lgB;
#pragma unroll
            for (int i = 0; i < 8; i++) {
                int c = wq + 4 * i;                   // 0..31
                if (c < 28) {
                    int t = ws + c;
                    float lg = (chunk_of(t) == chA) ? lgA : lgB;
                    ti[pl * CH + c] = g_LT[t * BATCH + b] + lg - LLc;
                } else {
                    ti[pl * CH + 63 + (c - 28)] = g_St[(c - 28) * BATCH + b];
                }
            }
        }
        // part B1: 35 X channels, lanes span c (coalesced row-major reads)
        for (int i = tid; i < 64 * 35; i += 256) {
            int bl = i / 35;
            int c  = i - bl * 35;
            ti[bl * CH + 28 + c] = X[(b0 + bl) * NTIME + ws + c];
        }
        // part B2: 7 outsample-Y channels (linear tile == output order)
#pragma unroll
        for (int p = 0; p < 2; p++) {
            int i = tid + 256 * p;
            if (i < 64 * OCH) {
                int bl = i / OCH;
                int c  = i - bl * OCH;
                to[i] = Y[(b0 + bl) * NTIME + ws + 28 + c];
            }
        }
        __syncthreads();

        // phase 2: straight float4 copies, streaming stores
        const float4* ti4 = (const float4*)ti;
        float4* ins4 = (float4*)(ins + (long long)bw0 * CH);   // 1072 float4
#pragma unroll
        for (int p = 0; p < 4; p++) {
            int j = tid + 256 * p;
            __stcs(&ins4[j], ti4[j]);
        }
        {
            int j = tid + 1024;
            if (j < 1072) __stcs(&ins4[j], ti4[j]);
        }
        if (tid < 112) {
            float4* outs4 = (float4*)(outs + (long long)bw0 * OCH);
            __stcs(&outs4[tid], ((const float4*)to)[tid]);
        }
    } else {
        // ================= fix role =================
        float* sm = pool;                 // 64*SP floats fits in pool
        int fid = blockIdx.x - NWIN;      // 0 .. NFIX-1
        int bx  = fid % 65;
        int b0  = (fid / 65) * 64;
        if (bx < 32) {
            int t0 = bx * 64;
#pragma unroll
            for (int p = 0; p < 4; p++) {        // load: rows = t, cols = b (f4)
                int f  = tid + 256 * p;
                int r  = f >> 4;
                int c4 = f & 15;
                float4 v = __ldcs((const float4*)&g_levT[(long long)(t0 + r) * BATCH + b0 + 4 * c4]);
                sm[(4 * c4 + 0) * SP + r] = v.x;
                sm[(4 * c4 + 1) * SP + r] = v.y;
                sm[(4 * c4 + 2) * SP + r] = v.z;
                sm[(4 * c4 + 3) * SP + r] = v.w;
            }
            __syncthreads();
#pragma unroll
            for (int p = 0; p < 4; p++) {        // store: rows = b, cols = t (f4)
                int f  = tid + 256 * p;
                int bb = f >> 4;
                int c4 = f & 15;
                int b  = b0 + bb;
                int t  = t0 + 4 * c4;
                float4 v = *(const float4*)&sm[bb * SP + 4 * c4];
                v.x *= g_gamma[chunk_of(t + 0) * BATCH + b];
                v.y *= g_gamma[chunk_of(t + 1) * BATCH + b];
                v.z *= g_gamma[chunk_of(t + 2) * BATCH + b];
                v.w *= g_gamma[chunk_of(t + 3) * BATCH + b];
                __stcs((float4*)&levels[(long long)b * NTIME + t], v);
            }
        } else {
            int j0 = (bx - 32) * 64;             // 33 x-tiles cover 2055
#pragma unroll
            for (int p = 0; p < 4; p++) {
                int f  = tid + 256 * p;
                int r  = f >> 4;
                int c4 = f & 15;
                int j  = j0 + r;
                if (j < SEASLEN) {
                    float4 v = __ldcs((const float4*)&g_seaT[(long long)j * BATCH + b0 + 4 * c4]);
                    sm[(4 * c4 + 0) * SP + r] = v.x;
                    sm[(4 * c4 + 1) * SP + r] = v.y;
                    sm[(4 * c4 + 2) * SP + r] = v.z;
                    sm[(4 * c4 + 3) * SP + r] = v.w;
                }
            }
            __syncthreads();
#pragma unroll
            for (int q = 0; q < 16; q++) {       // scalar coalesced stores
                int f  = tid + 256 * q;          // 4096 elements
                int bb = f >> 6;
                int jj = f & 63;
                int j  = j0 + jj;
                if (j >= SEASLEN) continue;
                int b = b0 + bb;
                float v = sm[bb * SP + jj];
                if (j >= 8)                      // seasonal[8+k] written at t=k+1
                    v *= g_rgam[chunk_of(j - 7) * BATCH + b];
                __stcs(&seasonal[(long long)b * SEASLEN + j], v);
            }
        }
    }
}

// ---------------- launch -----------------------------------------------------
extern "C" void kernel_launch(void* const* d_in, const int* in_sizes, int n_in,
                              void* d_out, int out_size)
{
    const float* S    = (const float*)d_in[0];   // (2048, 4)
    const float* Y    = (const float*)d_in[1];   // (2048, 2048)
    const float* X    = (const float*)d_in[2];   // (2048, 1, 2048)
    const int*   idxs = (const int*)  d_in[3];   // (2048,)
    const float* emb  = (const float*)d_in[4];   // (100000, 9)

    float* out      = (float*)d_out;
    float* ins      = out;                                      // 39,518,208
    float* outs     = out + INS_ELEMS;                          //  4,128,768
    float* levels   = out + INS_ELEMS + OUTS_ELEMS;             //  4,194,304
    float* seasonal = out + INS_ELEMS + OUTS_ELEMS + LEV_ELEMS; // 2048*2055

    transpose_Y  <<<dim3(32, 32), 256>>>(Y);                    // 1
    es_scan      <<<dim3(BATCH / 128, NC), 128>>>(idxs, emb);   // 2
    combine_gamma<<<BATCH / 256, 256>>>(S);                     // 3
    win_and_fix  <<<NWIN + NFIX, 256>>>(X, Y, ins, outs,        // 4 (ncu slot)
                                        levels, seasonal);
}